// round 1
// baseline (speedup 1.0000x reference)
#include <cuda_runtime.h>
#include <math.h>

#define BDIM 2
#define SEQ 2048
#define DMODEL 2048
#define NH 16
#define NKV 4
#define HD 128
#define NMOD 2
#define R_TOK (BDIM*SEQ)      /* 4096 tokens */
#define KVE (NKV*HD)          /* 512 */

/* ---------------- scratch (static device memory; no allocs) ---------------- */
__device__ float g_wk[NMOD*DMODEL*KVE];          /* summed Wk: 8MB */
__device__ float g_wv[NMOD*DMODEL*KVE];          /* summed Wv: 8MB */
__device__ float g_q[(size_t)BDIM*NH*SEQ*HD];    /* 32MB, [b][h][s][d] */
__device__ float g_k[(size_t)BDIM*NKV*SEQ*HD];   /* 8MB,  [b][kvh][s][d] */
__device__ float g_v[(size_t)BDIM*NKV*SEQ*HD];   /* 8MB,  [b][kvh][s][d] */
__device__ float g_attn[(size_t)BDIM*SEQ*DMODEL];/* 32MB, [b][s][h*HD+d] */

/* ---------------- Wk/Wv sum over second modality axis ---------------- */
__global__ void wsum_kernel(const float* __restrict__ Wk,
                            const float* __restrict__ Wv) {
    const int n = NMOD * DMODEL * KVE;          /* 2,097,152 */
    const int half = DMODEL * KVE;              /* 1,048,576 */
    for (int i = blockIdx.x * blockDim.x + threadIdx.x; i < n;
         i += gridDim.x * blockDim.x) {
        int m = i / half;
        int rest = i - m * half;
        size_t base = (size_t)m * 2 * half + rest;
        g_wk[i] = Wk[base] + Wk[base + half];
        g_wv[i] = Wv[base] + Wv[base + half];
    }
}

/* ---------------- 64x64 tile fp32 GEMM core ----------------
 * X: [rows, ldx] row-major; W: [Kdim, ldw] row-major.
 * 256 threads, 4x4 microtile each. As padded to 65 to kill conflicts. */
__device__ __forceinline__ void gemm64x64(
    const float* __restrict__ X, int ldx,
    const float* __restrict__ W, int ldw,
    int Kdim, int row0, int col0,
    float (&acc)[4][4], float* As, float* Bs)
{
    const int tid = threadIdx.x;
    const int tx = tid & 15, ty = tid >> 4;
    const int ar = tid >> 2;            /* 0..63  A row */
    const int ac = (tid & 3) << 2;      /* 0,4,8,12  A k-chunk */
    const int bk = tid >> 4;            /* 0..15  B k-row */
    const int bc = (tid & 15) << 2;     /* 0..60  B col chunk */

    for (int k0 = 0; k0 < Kdim; k0 += 16) {
        float4 av = *(const float4*)&X[(size_t)(row0 + ar) * ldx + k0 + ac];
        As[(ac + 0) * 65 + ar] = av.x;
        As[(ac + 1) * 65 + ar] = av.y;
        As[(ac + 2) * 65 + ar] = av.z;
        As[(ac + 3) * 65 + ar] = av.w;
        *(float4*)&Bs[bk * 64 + bc] =
            *(const float4*)&W[(size_t)(k0 + bk) * ldw + col0 + bc];
        __syncthreads();
        #pragma unroll
        for (int kk = 0; kk < 16; kk++) {
            float a[4];
            #pragma unroll
            for (int i = 0; i < 4; i++) a[i] = As[kk * 65 + ty * 4 + i];
            float4 bv = *(float4*)&Bs[kk * 64 + tx * 4];
            float bb[4] = {bv.x, bv.y, bv.z, bv.w};
            #pragma unroll
            for (int i = 0; i < 4; i++)
                #pragma unroll
                for (int j = 0; j < 4; j++)
                    acc[i][j] += a[i] * bb[j];
        }
        __syncthreads();
    }
}

/* ---------------- Q projection + RoPE ---------------- */
__global__ void __launch_bounds__(256) proj_q_kernel(
    const float* __restrict__ x, const float* __restrict__ Wq,
    const float* __restrict__ fc, const int* __restrict__ mid)
{
    __shared__ float As[16 * 65];
    __shared__ float Bs[16 * 64];
    const int m = blockIdx.z;
    const int row0 = blockIdx.y * 64;
    const int col0 = blockIdx.x * 64;
    float acc[4][4] = {};
    gemm64x64(x, DMODEL, Wq + (size_t)m * DMODEL * DMODEL, DMODEL,
              DMODEL, row0, col0, acc, As, Bs);

    const int tx = threadIdx.x & 15, ty = threadIdx.x >> 4;
    #pragma unroll
    for (int i = 0; i < 4; i++) {
        int r = row0 + ty * 4 + i;
        if (mid[r] != m) continue;
        int b = r >> 11, s = r & (SEQ - 1);
        int c0 = col0 + tx * 4;
        #pragma unroll
        for (int j2 = 0; j2 < 4; j2 += 2) {
            int c = c0 + j2;
            int h = c >> 7, d = c & 127;
            int pr = d >> 1;
            float cv = fc[(size_t)s * 256 + pr * 4 + 0];
            float sv = fc[(size_t)s * 256 + pr * 4 + 2];
            float e = acc[i][j2], o = acc[i][j2 + 1];
            size_t base = (((size_t)b * NH + h) * SEQ + s) * HD + d;
            g_q[base]     = e * cv + o * sv;
            g_q[base + 1] = o * cv - e * sv;
        }
    }
}

/* ---------------- K/V projection (+RoPE on K) ---------------- */
__global__ void __launch_bounds__(256) proj_kv_kernel(
    const float* __restrict__ x, const float* __restrict__ fc,
    const int* __restrict__ mid)
{
    __shared__ float As[16 * 65];
    __shared__ float Bs[16 * 64];
    const int m = blockIdx.z;
    const int row0 = blockIdx.y * 64;
    const int n0 = blockIdx.x * 64;           /* 0..960; >=512 -> V */
    const bool isV = (n0 >= KVE);
    const float* W = (isV ? g_wv : g_wk) + (size_t)m * DMODEL * KVE;
    const int c0base = isV ? n0 - KVE : n0;

    float acc[4][4] = {};
    gemm64x64(x, DMODEL, W, KVE, DMODEL, row0, c0base, acc, As, Bs);

    const int tx = threadIdx.x & 15, ty = threadIdx.x >> 4;
    #pragma unroll
    for (int i = 0; i < 4; i++) {
        int r = row0 + ty * 4 + i;
        if (mid[r] != m) continue;
        int b = r >> 11, s = r & (SEQ - 1);
        int c0 = c0base + tx * 4;
        if (!isV) {
            #pragma unroll
            for (int j2 = 0; j2 < 4; j2 += 2) {
                int c = c0 + j2;
                int kvh = c >> 7, d = c & 127;
                int pr = d >> 1;
                float cv = fc[(size_t)s * 256 + pr * 4 + 0];
                float sv = fc[(size_t)s * 256 + pr * 4 + 2];
                float e = acc[i][j2], o = acc[i][j2 + 1];
                size_t base = (((size_t)b * NKV + kvh) * SEQ + s) * HD + d;
                g_k[base]     = e * cv + o * sv;
                g_k[base + 1] = o * cv - e * sv;
            }
        } else {
            #pragma unroll
            for (int j = 0; j < 4; j++) {
                int c = c0 + j;
                int kvh = c >> 7, d = c & 127;
                g_v[(((size_t)b * NKV + kvh) * SEQ + s) * HD + d] = acc[i][j];
            }
        }
    }
}

/* ---------------- flash attention (non-causal), 64q x 64k tiles ----------------
 * smem: Qst[128][68] (transposed, pre-scaled), Kst[128][68] (transposed),
 *       Vs[64][132], Ps[64][68].  256 thr: scores 4x4/thr, O 4x8/thr. */
#define QPAD 68
#define VPAD 132
#define ATTN_SMEM ((128*QPAD + 128*QPAD + 64*VPAD + 64*QPAD) * 4)

__global__ void __launch_bounds__(256) attn_kernel() {
    extern __shared__ float sm[];
    float* Qst = sm;
    float* Kst = Qst + 128 * QPAD;
    float* Vs  = Kst + 128 * QPAD;
    float* Ps  = Vs + 64 * VPAD;

    const int qt = blockIdx.x, h = blockIdx.y, b = blockIdx.z;
    const int kvh = h >> 2;
    const int tid = threadIdx.x, tx = tid & 15, ty = tid >> 4;
    const float scale = 0.08838834764831845f;   /* 1/sqrt(128) */

    const float* Qg = g_q + (((size_t)b * NH + h) * SEQ + qt * 64) * HD;
    for (int i = tid; i < 64 * 128; i += 256) {
        int r = i >> 7, d = i & 127;
        Qst[d * QPAD + r] = Qg[i] * scale;
    }

    float mo[4], l[4], o[4][8];
    #pragma unroll
    for (int i = 0; i < 4; i++) {
        mo[i] = -1e30f; l[i] = 0.f;
        #pragma unroll
        for (int j = 0; j < 8; j++) o[i][j] = 0.f;
    }

    const float* Kg = g_k + ((size_t)b * NKV + kvh) * SEQ * HD;
    const float* Vg = g_v + ((size_t)b * NKV + kvh) * SEQ * HD;

    for (int kt = 0; kt < SEQ / 64; kt++) {
        __syncthreads();   /* prev iter done with Vs/Ps; first iter: Qst ready fence below */
        for (int i = tid; i < 64 * 128; i += 256) {
            int r = i >> 7, d = i & 127;
            float kv = Kg[(size_t)kt * 64 * 128 + i];
            float vv = Vg[(size_t)kt * 64 * 128 + i];
            Kst[d * QPAD + r] = kv;
            Vs[r * VPAD + d] = vv;
        }
        __syncthreads();

        /* scores 4x4 */
        float s4[4][4] = {};
        #pragma unroll 8
        for (int d = 0; d < 128; d++) {
            float4 av = *(float4*)&Qst[d * QPAD + ty * 4];
            float4 bv = *(float4*)&Kst[d * QPAD + tx * 4];
            float a[4] = {av.x, av.y, av.z, av.w};
            float bb[4] = {bv.x, bv.y, bv.z, bv.w};
            #pragma unroll
            for (int i = 0; i < 4; i++)
                #pragma unroll
                for (int j = 0; j < 4; j++)
                    s4[i][j] += a[i] * bb[j];
        }

        /* online softmax */
        #pragma unroll
        for (int i = 0; i < 4; i++) {
            float mx = fmaxf(fmaxf(s4[i][0], s4[i][1]), fmaxf(s4[i][2], s4[i][3]));
            mx = fmaxf(mx, __shfl_xor_sync(0xffffffffu, mx, 8));
            mx = fmaxf(mx, __shfl_xor_sync(0xffffffffu, mx, 4));
            mx = fmaxf(mx, __shfl_xor_sync(0xffffffffu, mx, 2));
            mx = fmaxf(mx, __shfl_xor_sync(0xffffffffu, mx, 1));
            float mnew = fmaxf(mo[i], mx);
            float corr = __expf(mo[i] - mnew);
            float rs = 0.f;
            #pragma unroll
            for (int j = 0; j < 4; j++) {
                float p = __expf(s4[i][j] - mnew);
                Ps[(ty * 4 + i) * QPAD + tx * 4 + j] = p;
                rs += p;
            }
            rs += __shfl_xor_sync(0xffffffffu, rs, 8);
            rs += __shfl_xor_sync(0xffffffffu, rs, 4);
            rs += __shfl_xor_sync(0xffffffffu, rs, 2);
            rs += __shfl_xor_sync(0xffffffffu, rs, 1);
            l[i] = l[i] * corr + rs;
            mo[i] = mnew;
            #pragma unroll
            for (int jj = 0; jj < 8; jj++) o[i][jj] *= corr;
        }
        __syncthreads();

        /* O += P @ V  (4 rows x 8 cols per thread) */
        #pragma unroll 2
        for (int kk = 0; kk < 64; kk++) {
            float4 v0 = *(float4*)&Vs[kk * VPAD + tx * 8];
            float4 v1 = *(float4*)&Vs[kk * VPAD + tx * 8 + 4];
            #pragma unroll
            for (int i = 0; i < 4; i++) {
                float p = Ps[(ty * 4 + i) * QPAD + kk];
                o[i][0] += p * v0.x; o[i][1] += p * v0.y;
                o[i][2] += p * v0.z; o[i][3] += p * v0.w;
                o[i][4] += p * v1.x; o[i][5] += p * v1.y;
                o[i][6] += p * v1.z; o[i][7] += p * v1.w;
            }
        }
    }

    float* Og = g_attn + ((size_t)b * SEQ + (size_t)qt * 64) * DMODEL + h * HD;
    #pragma unroll
    for (int i = 0; i < 4; i++) {
        float inv = 1.f / l[i];
        int r = ty * 4 + i;
        #pragma unroll
        for (int jj = 0; jj < 8; jj++)
            Og[(size_t)r * DMODEL + tx * 8 + jj] = o[i][jj] * inv;
    }
}

/* ---------------- output projection ---------------- */
__global__ void __launch_bounds__(256) proj_o_kernel(
    const float* __restrict__ Wo, const int* __restrict__ mid,
    float* __restrict__ out)
{
    __shared__ float As[16 * 65];
    __shared__ float Bs[16 * 64];
    const int m = blockIdx.z;
    const int row0 = blockIdx.y * 64;
    const int col0 = blockIdx.x * 64;
    float acc[4][4] = {};
    gemm64x64(g_attn, DMODEL, Wo + (size_t)m * DMODEL * DMODEL, DMODEL,
              DMODEL, row0, col0, acc, As, Bs);

    const int tx = threadIdx.x & 15, ty = threadIdx.x >> 4;
    #pragma unroll
    for (int i = 0; i < 4; i++) {
        int r = row0 + ty * 4 + i;
        if (mid[r] != m) continue;
        #pragma unroll
        for (int j = 0; j < 4; j++)
            out[(size_t)r * DMODEL + col0 + tx * 4 + j] = acc[i][j];
    }
}

/* ---------------- launch ---------------- */
extern "C" void kernel_launch(void* const* d_in, const int* in_sizes, int n_in,
                              void* d_out, int out_size) {
    (void)in_sizes; (void)n_in; (void)out_size;
    const float* x  = (const float*)d_in[0];
    const float* fc = (const float*)d_in[1];
    const float* Wq = (const float*)d_in[2];
    const float* Wk = (const float*)d_in[3];
    const float* Wv = (const float*)d_in[4];
    const float* Wo = (const float*)d_in[5];
    const int*   mid = (const int*)d_in[6];
    float* out = (float*)d_out;

    wsum_kernel<<<2048, 256>>>(Wk, Wv);
    proj_q_kernel<<<dim3(DMODEL / 64, R_TOK / 64, NMOD), 256>>>(x, Wq, fc, mid);
    proj_kv_kernel<<<dim3((2 * KVE) / 64, R_TOK / 64, NMOD), 256>>>(x, fc, mid);
    cudaFuncSetAttribute(attn_kernel,
                         cudaFuncAttributeMaxDynamicSharedMemorySize, ATTN_SMEM);
    attn_kernel<<<dim3(SEQ / 64, NH, BDIM), 256, ATTN_SMEM>>>();
    proj_o_kernel<<<dim3(DMODEL / 64, R_TOK / 64, NMOD), 256>>>(Wo, mid, out);
}

// round 2
// speedup vs baseline: 1.8706x; 1.8706x over previous
#include <cuda_runtime.h>
#include <math.h>

#define BDIM 2
#define SEQ 2048
#define DMODEL 2048
#define NH 16
#define NKV 4
#define HD 128
#define NMOD 2
#define R_TOK (BDIM*SEQ)      /* 4096 tokens */
#define KVE (NKV*HD)          /* 512 */

/* GEMM tiling */
#define BM 128
#define BN 128
#define BK 16
#define AP 20     /* A smem pitch (floats), row-major [m][k] */
#define BP 136    /* B smem pitch (floats), row-major [k][n] */
#define GEMM_SMEM_FLOATS (2*BM*AP + 2*BK*BP)

/* ---------------- scratch (static device memory; no allocs) ---------------- */
__device__ float g_wk[NMOD*DMODEL*KVE];            /* summed+tf32 Wk */
__device__ float g_wv[NMOD*DMODEL*KVE];            /* summed+tf32 Wv */
__device__ float g_xt[(size_t)R_TOK*DMODEL];       /* tf32-rounded x */
__device__ float g_wqt[(size_t)NMOD*DMODEL*DMODEL];/* tf32-rounded Wq */
__device__ float g_wot[(size_t)NMOD*DMODEL*DMODEL];/* tf32-rounded Wo */
__device__ float g_q[(size_t)BDIM*NH*SEQ*HD];      /* [b][h][s][d] */
__device__ float g_k[(size_t)BDIM*NKV*SEQ*HD];     /* [b][kvh][s][d] */
__device__ float g_v[(size_t)BDIM*NKV*SEQ*HD];     /* [b][kvh][s][d] */
__device__ float g_attn[(size_t)BDIM*SEQ*DMODEL];  /* [b][s][h*HD+d], tf32-rounded */

/* ---------------- helpers ---------------- */
__device__ __forceinline__ float f2t(float f) {
    unsigned u;
    asm("cvt.rna.tf32.f32 %0, %1;" : "=r"(u) : "f"(f));
    return __uint_as_float(u);
}

__device__ __forceinline__ void mma_tf32(float* d, const unsigned* a, const unsigned* b) {
    asm volatile(
        "mma.sync.aligned.m16n8k8.row.col.f32.tf32.tf32.f32 "
        "{%0,%1,%2,%3},{%4,%5,%6,%7},{%8,%9},{%0,%1,%2,%3};"
        : "+f"(d[0]), "+f"(d[1]), "+f"(d[2]), "+f"(d[3])
        : "r"(a[0]), "r"(a[1]), "r"(a[2]), "r"(a[3]), "r"(b[0]), "r"(b[1]));
}

#define CP16(dst, src) \
    asm volatile("cp.async.cg.shared.global [%0], [%1], 16;" :: "r"(dst), "l"(src))
#define CP_COMMIT() asm volatile("cp.async.commit_group;")
#define CP_WAIT(n)  asm volatile("cp.async.wait_group %0;" :: "n"(n))

/* ---------------- prepass: tf32-round x, Wq, Wo ---------------- */
__global__ void prep_kernel(const float* __restrict__ x,
                            const float* __restrict__ Wq,
                            const float* __restrict__ Wo) {
    const int NE = R_TOK * DMODEL;                 /* 8,388,608 (== 2*D*D) */
    for (int i = blockIdx.x * blockDim.x + threadIdx.x; i < 3 * NE;
         i += gridDim.x * blockDim.x) {
        if (i < NE)            g_xt[i]          = f2t(x[i]);
        else if (i < 2 * NE)   g_wqt[i - NE]    = f2t(Wq[i - NE]);
        else                   g_wot[i - 2*NE]  = f2t(Wo[i - 2*NE]);
    }
}

/* ---------------- Wk/Wv modality-sum (+tf32 round) ---------------- */
__global__ void wsum_kernel(const float* __restrict__ Wk,
                            const float* __restrict__ Wv) {
    const int n = NMOD * DMODEL * KVE;
    const int half = DMODEL * KVE;
    for (int i = blockIdx.x * blockDim.x + threadIdx.x; i < n;
         i += gridDim.x * blockDim.x) {
        int m = i / half;
        int rest = i - m * half;
        size_t base = (size_t)m * 2 * half + rest;
        g_wk[i] = f2t(Wk[base] + Wk[base + half]);
        g_wv[i] = f2t(Wv[base] + Wv[base + half]);
    }
}

/* ---------------- tf32 tensor-core GEMM core (128x128x16, 8 warps) ----------
 * X: [rows, ldx] row-major (tf32-rounded fp32); W: [Kdim, ldw] row-major.
 * Each warp computes 64x32 via 4x4 grid of m16n8k8 mma. cp.async double buffer. */
__device__ __forceinline__ void gemm_tf32(
    const float* __restrict__ X, int ldx,
    const float* __restrict__ W, int ldw,
    int Kdim, int row0, int col0,
    float (&acc)[4][4][4], float* smem)
{
    const int tid = threadIdx.x;
    const int lane = tid & 31, w = tid >> 5;
    const int wm = (w >> 2) * 64, wn = (w & 3) * 32;
    const int gid = lane >> 2, tig = lane & 3;

    float* As = smem;                     /* 2 * BM*AP floats */
    float* Bs = smem + 2 * BM * AP;       /* 2 * BK*BP floats */
    const unsigned sA = (unsigned)__cvta_generic_to_shared(As);
    const unsigned sB = (unsigned)__cvta_generic_to_shared(Bs);

    /* per-thread copy slots: 2 A float4 + 2 B float4 */
    const int fa0 = tid, fa1 = tid + 256;

    auto issue = [&](int buf, int k0) {
        unsigned aBase = sA + (unsigned)buf * (BM * AP * 4);
        unsigned bBase = sB + (unsigned)buf * (BK * BP * 4);
        {
            int fa = fa0;
            CP16(aBase + ((fa >> 2) * AP + (fa & 3) * 4) * 4,
                 &X[(size_t)(row0 + (fa >> 2)) * ldx + k0 + (fa & 3) * 4]);
            CP16(bBase + ((fa >> 5) * BP + (fa & 31) * 4) * 4,
                 &W[(size_t)(k0 + (fa >> 5)) * ldw + col0 + (fa & 31) * 4]);
        }
        {
            int fa = fa1;
            CP16(aBase + ((fa >> 2) * AP + (fa & 3) * 4) * 4,
                 &X[(size_t)(row0 + (fa >> 2)) * ldx + k0 + (fa & 3) * 4]);
            CP16(bBase + ((fa >> 5) * BP + (fa & 31) * 4) * 4,
                 &W[(size_t)(k0 + (fa >> 5)) * ldw + col0 + (fa & 31) * 4]);
        }
        CP_COMMIT();
    };

    issue(0, 0);
    const int T = Kdim / BK;
    for (int t = 0; t < T; t++) {
        const int buf = t & 1;
        if (t + 1 < T) { issue(buf ^ 1, (t + 1) * BK); CP_WAIT(1); }
        else           { CP_WAIT(0); }
        __syncthreads();

        const float* Ab = As + buf * (BM * AP);
        const float* Bb = Bs + buf * (BK * BP);
        #pragma unroll
        for (int kb = 0; kb < BK; kb += 8) {
            unsigned a[4][4], b[4][2];
            #pragma unroll
            for (int i = 0; i < 4; i++) {
                const float* ap = &Ab[(wm + i * 16 + gid) * AP + kb + tig];
                a[i][0] = __float_as_uint(ap[0]);
                a[i][1] = __float_as_uint(ap[8 * AP]);
                a[i][2] = __float_as_uint(ap[4]);
                a[i][3] = __float_as_uint(ap[8 * AP + 4]);
            }
            #pragma unroll
            for (int j = 0; j < 4; j++) {
                const float* bp = &Bb[(kb + tig) * BP + wn + j * 8 + gid];
                b[j][0] = __float_as_uint(bp[0]);
                b[j][1] = __float_as_uint(bp[4 * BP]);
            }
            #pragma unroll
            for (int i = 0; i < 4; i++)
                #pragma unroll
                for (int j = 0; j < 4; j++)
                    mma_tf32(acc[i][j], a[i], b[j]);
        }
        __syncthreads();
    }
}

/* fragment->global mapping:
 * row = row0 + wm + i*16 + gid + (half? 8 : 0)
 * col = col0 + wn + j*8 + tig*2  (+1 for odd element)
 * acc[i][j][half*2 + {0,1}] = (row, col), (row, col+1)  */

/* ---------------- Q projection + RoPE ---------------- */
__global__ void __launch_bounds__(256, 2) proj_q_kernel(
    const float* __restrict__ fc, const int* __restrict__ mid)
{
    __shared__ float smem[GEMM_SMEM_FLOATS];
    const int m = blockIdx.z;
    const int row0 = blockIdx.y * BM, col0 = blockIdx.x * BN;
    float acc[4][4][4] = {};
    gemm_tf32(g_xt, DMODEL, g_wqt + (size_t)m * DMODEL * DMODEL, DMODEL,
              DMODEL, row0, col0, acc, smem);

    const int lane = threadIdx.x & 31, w = threadIdx.x >> 5;
    const int wm = (w >> 2) * 64, wn = (w & 3) * 32;
    const int gid = lane >> 2, tig = lane & 3;
    #pragma unroll
    for (int i = 0; i < 4; i++) {
        #pragma unroll
        for (int half = 0; half < 2; half++) {
            int r = row0 + wm + i * 16 + gid + half * 8;
            if (mid[r] != m) continue;
            int b_ = r >> 11, s = r & (SEQ - 1);
            #pragma unroll
            for (int j = 0; j < 4; j++) {
                int c = col0 + wn + j * 8 + tig * 2;
                float e = acc[i][j][half * 2 + 0];
                float o = acc[i][j][half * 2 + 1];
                int h = c >> 7, d = c & 127, pr = d >> 1;
                float cv = fc[(size_t)s * 256 + pr * 4 + 0];
                float sv = fc[(size_t)s * 256 + pr * 4 + 2];
                size_t base = (((size_t)b_ * NH + h) * SEQ + s) * HD + d;
                g_q[base]     = e * cv + o * sv;
                g_q[base + 1] = o * cv - e * sv;
            }
        }
    }
}

/* ---------------- K/V projection (+RoPE on K) ---------------- */
__global__ void __launch_bounds__(256, 2) proj_kv_kernel(
    const float* __restrict__ fc, const int* __restrict__ mid)
{
    __shared__ float smem[GEMM_SMEM_FLOATS];
    const int m = blockIdx.z;
    const int row0 = blockIdx.y * BM;
    const int n0 = blockIdx.x * BN;            /* 0..896; >=512 -> V */
    const bool isV = (n0 >= KVE);
    const float* W = (isV ? g_wv : g_wk) + (size_t)m * DMODEL * KVE;
    const int c0base = isV ? n0 - KVE : n0;

    float acc[4][4][4] = {};
    gemm_tf32(g_xt, DMODEL, W, KVE, DMODEL, row0, c0base, acc, smem);

    const int lane = threadIdx.x & 31, w = threadIdx.x >> 5;
    const int wm = (w >> 2) * 64, wn = (w & 3) * 32;
    const int gid = lane >> 2, tig = lane & 3;
    #pragma unroll
    for (int i = 0; i < 4; i++) {
        #pragma unroll
        for (int half = 0; half < 2; half++) {
            int r = row0 + wm + i * 16 + gid + half * 8;
            if (mid[r] != m) continue;
            int b_ = r >> 11, s = r & (SEQ - 1);
            #pragma unroll
            for (int j = 0; j < 4; j++) {
                int c = c0base + wn + j * 8 + tig * 2;
                int kvh = c >> 7, d = c & 127;
                float e = acc[i][j][half * 2 + 0];
                float o = acc[i][j][half * 2 + 1];
                size_t base = (((size_t)b_ * NKV + kvh) * SEQ + s) * HD + d;
                if (!isV) {
                    int pr = d >> 1;
                    float cv = fc[(size_t)s * 256 + pr * 4 + 0];
                    float sv = fc[(size_t)s * 256 + pr * 4 + 2];
                    g_k[base]     = e * cv + o * sv;
                    g_k[base + 1] = o * cv - e * sv;
                } else {
                    g_v[base]     = e;
                    g_v[base + 1] = o;
                }
            }
        }
    }
}

/* ---------------- flash attention (non-causal, fp32), 64q x 64k tiles ------ */
#define QPAD 68
#define VPAD 132
#define ATTN_SMEM ((128*QPAD + 128*QPAD + 64*VPAD + 64*QPAD) * 4)

__global__ void __launch_bounds__(256) attn_kernel() {
    extern __shared__ float sm[];
    float* Qst = sm;
    float* Kst = Qst + 128 * QPAD;
    float* Vs  = Kst + 128 * QPAD;
    float* Ps  = Vs + 64 * VPAD;

    const int qt = blockIdx.x, h = blockIdx.y, b = blockIdx.z;
    const int kvh = h >> 2;
    const int tid = threadIdx.x, tx = tid & 15, ty = tid >> 4;
    const float scale = 0.08838834764831845f;

    const float* Qg = g_q + (((size_t)b * NH + h) * SEQ + qt * 64) * HD;
    for (int i = tid; i < 64 * 128; i += 256) {
        int r = i >> 7, d = i & 127;
        Qst[d * QPAD + r] = Qg[i] * scale;
    }

    float mo[4], l[4], o[4][8];
    #pragma unroll
    for (int i = 0; i < 4; i++) {
        mo[i] = -1e30f; l[i] = 0.f;
        #pragma unroll
        for (int j = 0; j < 8; j++) o[i][j] = 0.f;
    }

    const float* Kg = g_k + ((size_t)b * NKV + kvh) * SEQ * HD;
    const float* Vg = g_v + ((size_t)b * NKV + kvh) * SEQ * HD;

    for (int kt = 0; kt < SEQ / 64; kt++) {
        __syncthreads();
        for (int i = tid; i < 64 * 128; i += 256) {
            int r = i >> 7, d = i & 127;
            float kv = Kg[(size_t)kt * 64 * 128 + i];
            float vv = Vg[(size_t)kt * 64 * 128 + i];
            Kst[d * QPAD + r] = kv;
            Vs[r * VPAD + d] = vv;
        }
        __syncthreads();

        float s4[4][4] = {};
        #pragma unroll 8
        for (int d = 0; d < 128; d++) {
            float4 av = *(float4*)&Qst[d * QPAD + ty * 4];
            float4 bv = *(float4*)&Kst[d * QPAD + tx * 4];
            float a[4] = {av.x, av.y, av.z, av.w};
            float bb[4] = {bv.x, bv.y, bv.z, bv.w};
            #pragma unroll
            for (int i = 0; i < 4; i++)
                #pragma unroll
                for (int j = 0; j < 4; j++)
                    s4[i][j] += a[i] * bb[j];
        }

        #pragma unroll
        for (int i = 0; i < 4; i++) {
            float mx = fmaxf(fmaxf(s4[i][0], s4[i][1]), fmaxf(s4[i][2], s4[i][3]));
            mx = fmaxf(mx, __shfl_xor_sync(0xffffffffu, mx, 8));
            mx = fmaxf(mx, __shfl_xor_sync(0xffffffffu, mx, 4));
            mx = fmaxf(mx, __shfl_xor_sync(0xffffffffu, mx, 2));
            mx = fmaxf(mx, __shfl_xor_sync(0xffffffffu, mx, 1));
            float mnew = fmaxf(mo[i], mx);
            float corr = __expf(mo[i] - mnew);
            float rs = 0.f;
            #pragma unroll
            for (int j = 0; j < 4; j++) {
                float p = __expf(s4[i][j] - mnew);
                Ps[(ty * 4 + i) * QPAD + tx * 4 + j] = p;
                rs += p;
            }
            rs += __shfl_xor_sync(0xffffffffu, rs, 8);
            rs += __shfl_xor_sync(0xffffffffu, rs, 4);
            rs += __shfl_xor_sync(0xffffffffu, rs, 2);
            rs += __shfl_xor_sync(0xffffffffu, rs, 1);
            l[i] = l[i] * corr + rs;
            mo[i] = mnew;
            #pragma unroll
            for (int jj = 0; jj < 8; jj++) o[i][jj] *= corr;
        }
        __syncthreads();

        #pragma unroll 2
        for (int kk = 0; kk < 64; kk++) {
            float4 v0 = *(float4*)&Vs[kk * VPAD + tx * 8];
            float4 v1 = *(float4*)&Vs[kk * VPAD + tx * 8 + 4];
            #pragma unroll
            for (int i = 0; i < 4; i++) {
                float p = Ps[(ty * 4 + i) * QPAD + kk];
                o[i][0] += p * v0.x; o[i][1] += p * v0.y;
                o[i][2] += p * v0.z; o[i][3] += p * v0.w;
                o[i][4] += p * v1.x; o[i][5] += p * v1.y;
                o[i][6] += p * v1.z; o[i][7] += p * v1.w;
            }
        }
    }

    float* Og = g_attn + ((size_t)b * SEQ + (size_t)qt * 64) * DMODEL + h * HD;
    #pragma unroll
    for (int i = 0; i < 4; i++) {
        float inv = 1.f / l[i];
        int r = ty * 4 + i;
        #pragma unroll
        for (int jj = 0; jj < 8; jj++)
            Og[(size_t)r * DMODEL + tx * 8 + jj] = f2t(o[i][jj] * inv);
    }
}

/* ---------------- output projection ---------------- */
__global__ void __launch_bounds__(256, 2) proj_o_kernel(
    const int* __restrict__ mid, float* __restrict__ out)
{
    __shared__ float smem[GEMM_SMEM_FLOATS];
    const int m = blockIdx.z;
    const int row0 = blockIdx.y * BM, col0 = blockIdx.x * BN;
    float acc[4][4][4] = {};
    gemm_tf32(g_attn, DMODEL, g_wot + (size_t)m * DMODEL * DMODEL, DMODEL,
              DMODEL, row0, col0, acc, smem);

    const int lane = threadIdx.x & 31, w = threadIdx.x >> 5;
    const int wm = (w >> 2) * 64, wn = (w & 3) * 32;
    const int gid = lane >> 2, tig = lane & 3;
    #pragma unroll
    for (int i = 0; i < 4; i++) {
        #pragma unroll
        for (int half = 0; half < 2; half++) {
            int r = row0 + wm + i * 16 + gid + half * 8;
            if (mid[r] != m) continue;
            #pragma unroll
            for (int j = 0; j < 4; j++) {
                int c = col0 + wn + j * 8 + tig * 2;
                out[(size_t)r * DMODEL + c]     = acc[i][j][half * 2 + 0];
                out[(size_t)r * DMODEL + c + 1] = acc[i][j][half * 2 + 1];
            }
        }
    }
}

/* ---------------- launch ---------------- */
extern "C" void kernel_launch(void* const* d_in, const int* in_sizes, int n_in,
                              void* d_out, int out_size) {
    (void)in_sizes; (void)n_in; (void)out_size;
    const float* x  = (const float*)d_in[0];
    const float* fc = (const float*)d_in[1];
    const float* Wq = (const float*)d_in[2];
    const float* Wk = (const float*)d_in[3];
    const float* Wv = (const float*)d_in[4];
    const float* Wo = (const float*)d_in[5];
    const int*   mid = (const int*)d_in[6];
    float* out = (float*)d_out;

    prep_kernel<<<4096, 256>>>(x, Wq, Wo);
    wsum_kernel<<<2048, 256>>>(Wk, Wv);
    proj_q_kernel<<<dim3(DMODEL / BN, R_TOK / BM, NMOD), 256>>>(fc, mid);
    proj_kv_kernel<<<dim3((2 * KVE) / BN, R_TOK / BM, NMOD), 256>>>(fc, mid);
    cudaFuncSetAttribute(attn_kernel,
                         cudaFuncAttributeMaxDynamicSharedMemorySize, ATTN_SMEM);
    attn_kernel<<<dim3(SEQ / 64, NH, BDIM), 256, ATTN_SMEM>>>();
    proj_o_kernel<<<dim3(DMODEL / BN, R_TOK / BM, NMOD), 256>>>(mid, out);
}

// round 3
// speedup vs baseline: 3.2780x; 1.7524x over previous
#include <cuda_runtime.h>
#include <math.h>

#define BDIM 2
#define SEQ 2048
#define DMODEL 2048
#define NH 16
#define NKV 4
#define HD 128
#define NMOD 2
#define R_TOK (BDIM*SEQ)      /* 4096 tokens */
#define KVE (NKV*HD)          /* 512 */

/* GEMM tiling */
#define BM 128
#define BN 128
#define BK 16
#define AP 20     /* A smem pitch (floats) */
#define BP 136    /* B smem pitch (floats) */
#define GEMM_SMEM_FLOATS (2*BM*AP + 2*BK*BP)

/* ---------------- scratch ---------------- */
__device__ float g_wk[NMOD*DMODEL*KVE];
__device__ float g_wv[NMOD*DMODEL*KVE];
__device__ float g_xt[(size_t)R_TOK*DMODEL];
__device__ float g_wqt[(size_t)NMOD*DMODEL*DMODEL];
__device__ float g_wot[(size_t)NMOD*DMODEL*DMODEL];
__device__ float g_q[(size_t)BDIM*NH*SEQ*HD];
__device__ float g_k[(size_t)BDIM*NKV*SEQ*HD];
__device__ float g_v[(size_t)BDIM*NKV*SEQ*HD];
__device__ float g_attn[(size_t)BDIM*SEQ*DMODEL];   /* full fp32 now */

/* ---------------- helpers ---------------- */
__device__ __forceinline__ float f2t(float f) {
    unsigned u;
    asm("cvt.rna.tf32.f32 %0, %1;" : "=r"(u) : "f"(f));
    return __uint_as_float(u);
}
__device__ __forceinline__ unsigned f2tu(float f) {
    unsigned u;
    asm("cvt.rna.tf32.f32 %0, %1;" : "=r"(u) : "f"(f));
    return u;
}
__device__ __forceinline__ void mma_tf32(float* d, const unsigned* a, const unsigned* b) {
    asm volatile(
        "mma.sync.aligned.m16n8k8.row.col.f32.tf32.tf32.f32 "
        "{%0,%1,%2,%3},{%4,%5,%6,%7},{%8,%9},{%0,%1,%2,%3};"
        : "+f"(d[0]), "+f"(d[1]), "+f"(d[2]), "+f"(d[3])
        : "r"(a[0]), "r"(a[1]), "r"(a[2]), "r"(a[3]), "r"(b[0]), "r"(b[1]));
}

#define CP16(dst, src) \
    asm volatile("cp.async.cg.shared.global [%0], [%1], 16;" :: "r"(dst), "l"(src))
#define CP_COMMIT() asm volatile("cp.async.commit_group;")
#define CP_WAIT(n)  asm volatile("cp.async.wait_group %0;" :: "n"(n))

/* ---------------- prepass: tf32-round x, Wq, Wo ---------------- */
__global__ void prep_kernel(const float* __restrict__ x,
                            const float* __restrict__ Wq,
                            const float* __restrict__ Wo) {
    const int NE = R_TOK * DMODEL;
    for (int i = blockIdx.x * blockDim.x + threadIdx.x; i < 3 * NE;
         i += gridDim.x * blockDim.x) {
        if (i < NE)            g_xt[i]          = f2t(x[i]);
        else if (i < 2 * NE)   g_wqt[i - NE]    = f2t(Wq[i - NE]);
        else                   g_wot[i - 2*NE]  = f2t(Wo[i - 2*NE]);
    }
}

__global__ void wsum_kernel(const float* __restrict__ Wk,
                            const float* __restrict__ Wv) {
    const int n = NMOD * DMODEL * KVE;
    const int half = DMODEL * KVE;
    for (int i = blockIdx.x * blockDim.x + threadIdx.x; i < n;
         i += gridDim.x * blockDim.x) {
        int m = i / half;
        int rest = i - m * half;
        size_t base = (size_t)m * 2 * half + rest;
        g_wk[i] = f2t(Wk[base] + Wk[base + half]);
        g_wv[i] = f2t(Wv[base] + Wv[base + half]);
    }
}

/* ---------------- tf32 GEMM staging (shared by both variants) ------------- */
#define GEMM_STAGE_PROLOGUE()                                                 \
    const int tid = threadIdx.x;                                              \
    const int lane = tid & 31, w = tid >> 5;                                  \
    const int wm = (w >> 2) * 64, wn = (w & 3) * 32;                          \
    const int gid = lane >> 2, tig = lane & 3;                                \
    float* As = smem;                                                         \
    float* Bs = smem + 2 * BM * AP;                                           \
    const unsigned sA = (unsigned)__cvta_generic_to_shared(As);               \
    const unsigned sB = (unsigned)__cvta_generic_to_shared(Bs);               \
    auto issue = [&](int buf, int k0) {                                       \
        unsigned aBase = sA + (unsigned)buf * (BM * AP * 4);                  \
        unsigned bBase = sB + (unsigned)buf * (BK * BP * 4);                  \
        for (int q = 0; q < 2; q++) {                                         \
            int fa = tid + q * 256;                                           \
            CP16(aBase + ((fa >> 2) * AP + (fa & 3) * 4) * 4,                 \
                 &X[(size_t)(row0 + (fa >> 2)) * ldx + k0 + (fa & 3) * 4]);   \
            CP16(bBase + ((fa >> 5) * BP + (fa & 31) * 4) * 4,                \
                 &W[(size_t)(k0 + (fa >> 5)) * ldw + col0 + (fa & 31) * 4]);  \
        }                                                                     \
        CP_COMMIT();                                                          \
    };

/* single-pass (X pre-rounded tf32) */
__device__ __forceinline__ void gemm_tf32(
    const float* __restrict__ X, int ldx,
    const float* __restrict__ W, int ldw,
    int Kdim, int row0, int col0,
    float (&acc)[4][4][4], float* smem)
{
    GEMM_STAGE_PROLOGUE();
    issue(0, 0);
    const int T = Kdim / BK;
    for (int t = 0; t < T; t++) {
        const int buf = t & 1;
        if (t + 1 < T) { issue(buf ^ 1, (t + 1) * BK); CP_WAIT(1); }
        else           { CP_WAIT(0); }
        __syncthreads();
        const float* Ab = As + buf * (BM * AP);
        const float* Bb = Bs + buf * (BK * BP);
        #pragma unroll
        for (int kb = 0; kb < BK; kb += 8) {
            unsigned a[4][4], b[4][2];
            #pragma unroll
            for (int i = 0; i < 4; i++) {
                const float* ap = &Ab[(wm + i * 16 + gid) * AP + kb + tig];
                a[i][0] = __float_as_uint(ap[0]);
                a[i][1] = __float_as_uint(ap[8 * AP]);
                a[i][2] = __float_as_uint(ap[4]);
                a[i][3] = __float_as_uint(ap[8 * AP + 4]);
            }
            #pragma unroll
            for (int j = 0; j < 4; j++) {
                const float* bp = &Bb[(kb + tig) * BP + wn + j * 8 + gid];
                b[j][0] = __float_as_uint(bp[0]);
                b[j][1] = __float_as_uint(bp[4 * BP]);
            }
            #pragma unroll
            for (int i = 0; i < 4; i++)
                #pragma unroll
                for (int j = 0; j < 4; j++)
                    mma_tf32(acc[i][j], a[i], b[j]);
        }
        __syncthreads();
    }
}

/* split-A 2-pass (X raw fp32; W pre-rounded tf32): D = Ah*W + Al*W */
__device__ __forceinline__ void gemm_tf32_splitA(
    const float* __restrict__ X, int ldx,
    const float* __restrict__ W, int ldw,
    int Kdim, int row0, int col0,
    float (&acc)[4][4][4], float* smem)
{
    GEMM_STAGE_PROLOGUE();
    issue(0, 0);
    const int T = Kdim / BK;
    for (int t = 0; t < T; t++) {
        const int buf = t & 1;
        if (t + 1 < T) { issue(buf ^ 1, (t + 1) * BK); CP_WAIT(1); }
        else           { CP_WAIT(0); }
        __syncthreads();
        const float* Ab = As + buf * (BM * AP);
        const float* Bb = Bs + buf * (BK * BP);
        #pragma unroll
        for (int kb = 0; kb < BK; kb += 8) {
            unsigned b[4][2];
            #pragma unroll
            for (int j = 0; j < 4; j++) {
                const float* bp = &Bb[(kb + tig) * BP + wn + j * 8 + gid];
                b[j][0] = __float_as_uint(bp[0]);
                b[j][1] = __float_as_uint(bp[4 * BP]);
            }
            #pragma unroll
            for (int i = 0; i < 4; i++) {
                const float* ap = &Ab[(wm + i * 16 + gid) * AP + kb + tig];
                float v[4] = {ap[0], ap[8 * AP], ap[4], ap[8 * AP + 4]};
                unsigned ah[4], al[4];
                #pragma unroll
                for (int q = 0; q < 4; q++) {
                    ah[q] = f2tu(v[q]);
                    al[q] = f2tu(v[q] - __uint_as_float(ah[q]));
                }
                #pragma unroll
                for (int j = 0; j < 4; j++) {
                    mma_tf32(acc[i][j], ah, b[j]);
                    mma_tf32(acc[i][j], al, b[j]);
                }
            }
        }
        __syncthreads();
    }
}

/* ---------------- Q projection + RoPE ---------------- */
__global__ void __launch_bounds__(256, 2) proj_q_kernel(
    const float* __restrict__ fc, const int* __restrict__ mid)
{
    __shared__ float smem[GEMM_SMEM_FLOATS];
    const int m = blockIdx.z;
    const int row0 = blockIdx.y * BM, col0 = blockIdx.x * BN;
    float acc[4][4][4] = {};
    gemm_tf32(g_xt, DMODEL, g_wqt + (size_t)m * DMODEL * DMODEL, DMODEL,
              DMODEL, row0, col0, acc, smem);

    const int lane = threadIdx.x & 31, w = threadIdx.x >> 5;
    const int wm = (w >> 2) * 64, wn = (w & 3) * 32;
    const int gid = lane >> 2, tig = lane & 3;
    #pragma unroll
    for (int i = 0; i < 4; i++) {
        #pragma unroll
        for (int half = 0; half < 2; half++) {
            int r = row0 + wm + i * 16 + gid + half * 8;
            if (mid[r] != m) continue;
            int b_ = r >> 11, s = r & (SEQ - 1);
            #pragma unroll
            for (int j = 0; j < 4; j++) {
                int c = col0 + wn + j * 8 + tig * 2;
                float e = acc[i][j][half * 2 + 0];
                float o = acc[i][j][half * 2 + 1];
                int h = c >> 7, d = c & 127, pr = d >> 1;
                float cv = fc[(size_t)s * 256 + pr * 4 + 0];
                float sv = fc[(size_t)s * 256 + pr * 4 + 2];
                size_t base = (((size_t)b_ * NH + h) * SEQ + s) * HD + d;
                g_q[base]     = e * cv + o * sv;
                g_q[base + 1] = o * cv - e * sv;
            }
        }
    }
}

/* ---------------- K/V projection (+RoPE on K) ---------------- */
__global__ void __launch_bounds__(256, 2) proj_kv_kernel(
    const float* __restrict__ fc, const int* __restrict__ mid)
{
    __shared__ float smem[GEMM_SMEM_FLOATS];
    const int m = blockIdx.z;
    const int row0 = blockIdx.y * BM;
    const int n0 = blockIdx.x * BN;
    const bool isV = (n0 >= KVE);
    const float* W = (isV ? g_wv : g_wk) + (size_t)m * DMODEL * KVE;
    const int c0base = isV ? n0 - KVE : n0;

    float acc[4][4][4] = {};
    gemm_tf32(g_xt, DMODEL, W, KVE, DMODEL, row0, c0base, acc, smem);

    const int lane = threadIdx.x & 31, w = threadIdx.x >> 5;
    const int wm = (w >> 2) * 64, wn = (w & 3) * 32;
    const int gid = lane >> 2, tig = lane & 3;
    #pragma unroll
    for (int i = 0; i < 4; i++) {
        #pragma unroll
        for (int half = 0; half < 2; half++) {
            int r = row0 + wm + i * 16 + gid + half * 8;
            if (mid[r] != m) continue;
            int b_ = r >> 11, s = r & (SEQ - 1);
            #pragma unroll
            for (int j = 0; j < 4; j++) {
                int c = c0base + wn + j * 8 + tig * 2;
                int kvh = c >> 7, d = c & 127;
                float e = acc[i][j][half * 2 + 0];
                float o = acc[i][j][half * 2 + 1];
                size_t base = (((size_t)b_ * NKV + kvh) * SEQ + s) * HD + d;
                if (!isV) {
                    int pr = d >> 1;
                    float cv = fc[(size_t)s * 256 + pr * 4 + 0];
                    float sv = fc[(size_t)s * 256 + pr * 4 + 2];
                    g_k[base]     = e * cv + o * sv;
                    g_k[base + 1] = o * cv - e * sv;
                } else {
                    g_v[base]     = e;
                    g_v[base + 1] = o;
                }
            }
        }
    }
}

/* ---------------- flash attention, tf32 tensor cores ----------------------
 * CTA: 64 q-rows, 4 warps (m16 each). K/V tiles 64x128 in smem.
 * Q frags in registers (pre-scaled, rna-rounded). P via per-warp smem patch. */
#define KP 132
#define VP 136
#define PP 68
#define ATTN_SMEM ((64*KP + 64*VP + 64*PP) * 4)

__global__ void __launch_bounds__(128, 2) attn_kernel() {
    extern __shared__ float sm[];
    float* Ks = sm;
    float* Vs = Ks + 64 * KP;
    float* Ps = Vs + 64 * VP;

    const int qt = blockIdx.x, h = blockIdx.y, b = blockIdx.z;
    const int kvh = h >> 2;
    const int tid = threadIdx.x;
    const int w = tid >> 5, lane = tid & 31, gid = lane >> 2, tig = lane & 3;
    const float scale = 0.08838834764831845f;

    /* Q fragments: rows (gid, gid+8) of this warp's m16 slice, all 16 k-steps */
    const float* Qg = g_q + (((size_t)b * NH + h) * SEQ + qt * 64 + w * 16) * HD;
    unsigned QA[16][4];
    #pragma unroll
    for (int ks = 0; ks < 16; ks++) {
        QA[ks][0] = f2tu(Qg[gid * HD + 8 * ks + tig] * scale);
        QA[ks][1] = f2tu(Qg[(gid + 8) * HD + 8 * ks + tig] * scale);
        QA[ks][2] = f2tu(Qg[gid * HD + 8 * ks + tig + 4] * scale);
        QA[ks][3] = f2tu(Qg[(gid + 8) * HD + 8 * ks + tig + 4] * scale);
    }

    float o[16][4];
    #pragma unroll
    for (int n = 0; n < 16; n++)
        #pragma unroll
        for (int q = 0; q < 4; q++) o[n][q] = 0.f;
    float mo[2] = {-1e30f, -1e30f}, l[2] = {0.f, 0.f};

    const float* Kg = g_k + ((size_t)b * NKV + kvh) * SEQ * HD;
    const float* Vg = g_v + ((size_t)b * NKV + kvh) * SEQ * HD;
    float* Pw = Ps + w * 16 * PP;

    for (int kt = 0; kt < SEQ / 64; kt++) {
        __syncthreads();
        const float* Kt = Kg + (size_t)kt * 64 * HD;
        const float* Vt = Vg + (size_t)kt * 64 * HD;
        #pragma unroll
        for (int it = 0; it < 16; it++) {
            int i = tid + it * 128;
            int r = i >> 5, c4 = (i & 31) << 2;
            float4 kv4 = *(const float4*)&Kt[r * HD + c4];
            float4 vv4 = *(const float4*)&Vt[r * HD + c4];
            kv4.x = f2t(kv4.x); kv4.y = f2t(kv4.y);
            kv4.z = f2t(kv4.z); kv4.w = f2t(kv4.w);
            vv4.x = f2t(vv4.x); vv4.y = f2t(vv4.y);
            vv4.z = f2t(vv4.z); vv4.w = f2t(vv4.w);
            *(float4*)&Ks[r * KP + c4] = kv4;
            *(float4*)&Vs[r * VP + c4] = vv4;
        }
        __syncthreads();

        /* S = Q K^T : 16 k-steps x 8 n-blocks */
        float s[8][4] = {};
        #pragma unroll
        for (int ks = 0; ks < 16; ks++) {
            #pragma unroll
            for (int j = 0; j < 8; j++) {
                unsigned b2[2];
                b2[0] = __float_as_uint(Ks[(j * 8 + gid) * KP + ks * 8 + tig]);
                b2[1] = __float_as_uint(Ks[(j * 8 + gid) * KP + ks * 8 + tig + 4]);
                mma_tf32(s[j], QA[ks], b2);
            }
        }

        /* online softmax (exact fp32) */
        #pragma unroll
        for (int rr = 0; rr < 2; rr++) {
            float mx = -1e30f;
            #pragma unroll
            for (int j = 0; j < 8; j++)
                mx = fmaxf(mx, fmaxf(s[j][2 * rr], s[j][2 * rr + 1]));
            mx = fmaxf(mx, __shfl_xor_sync(0xffffffffu, mx, 1));
            mx = fmaxf(mx, __shfl_xor_sync(0xffffffffu, mx, 2));
            float mnew = fmaxf(mo[rr], mx);
            float corr = __expf(mo[rr] - mnew);
            float rs = 0.f;
            #pragma unroll
            for (int j = 0; j < 8; j++) {
                float p0 = f2t(__expf(s[j][2 * rr] - mnew));
                float p1 = f2t(__expf(s[j][2 * rr + 1] - mnew));
                s[j][2 * rr] = p0; s[j][2 * rr + 1] = p1;
                rs += p0 + p1;
            }
            rs += __shfl_xor_sync(0xffffffffu, rs, 1);
            rs += __shfl_xor_sync(0xffffffffu, rs, 2);
            l[rr] = l[rr] * corr + rs;
            mo[rr] = mnew;
            #pragma unroll
            for (int n = 0; n < 16; n++) {
                o[n][2 * rr] *= corr; o[n][2 * rr + 1] *= corr;
            }
        }

        /* P -> per-warp smem patch (acc layout -> A-frag layout roundtrip) */
        #pragma unroll
        for (int j = 0; j < 8; j++) {
            *(float2*)&Pw[gid * PP + j * 8 + 2 * tig] =
                make_float2(s[j][0], s[j][1]);
            *(float2*)&Pw[(gid + 8) * PP + j * 8 + 2 * tig] =
                make_float2(s[j][2], s[j][3]);
        }
        __syncwarp();

        /* O += P V : 8 k-steps x 16 n-blocks */
        #pragma unroll
        for (int kk = 0; kk < 8; kk++) {
            unsigned a[4];
            a[0] = __float_as_uint(Pw[gid * PP + kk * 8 + tig]);
            a[1] = __float_as_uint(Pw[(gid + 8) * PP + kk * 8 + tig]);
            a[2] = __float_as_uint(Pw[gid * PP + kk * 8 + tig + 4]);
            a[3] = __float_as_uint(Pw[(gid + 8) * PP + kk * 8 + tig + 4]);
            #pragma unroll
            for (int n = 0; n < 16; n++) {
                unsigned b2[2];
                b2[0] = __float_as_uint(Vs[(kk * 8 + tig) * VP + n * 8 + gid]);
                b2[1] = __float_as_uint(Vs[(kk * 8 + tig + 4) * VP + n * 8 + gid]);
                mma_tf32(o[n], a, b2);
            }
        }
    }

    /* epilogue: normalize and write [b][s][h*128+d] (full fp32) */
    float* Og = g_attn + ((size_t)b * SEQ + qt * 64 + w * 16) * DMODEL + h * HD;
    float inv0 = 1.f / l[0], inv1 = 1.f / l[1];
    #pragma unroll
    for (int n = 0; n < 16; n++) {
        *(float2*)&Og[gid * DMODEL + n * 8 + 2 * tig] =
            make_float2(o[n][0] * inv0, o[n][1] * inv0);
        *(float2*)&Og[(gid + 8) * DMODEL + n * 8 + 2 * tig] =
            make_float2(o[n][2] * inv1, o[n][3] * inv1);
    }
}

/* ---------------- output projection (split-A, 2-pass) ---------------- */
__global__ void __launch_bounds__(256, 2) proj_o_kernel(
    const int* __restrict__ mid, float* __restrict__ out)
{
    __shared__ float smem[GEMM_SMEM_FLOATS];
    const int m = blockIdx.z;
    const int row0 = blockIdx.y * BM, col0 = blockIdx.x * BN;
    float acc[4][4][4] = {};
    gemm_tf32_splitA(g_attn, DMODEL, g_wot + (size_t)m * DMODEL * DMODEL, DMODEL,
                     DMODEL, row0, col0, acc, smem);

    const int lane = threadIdx.x & 31, w = threadIdx.x >> 5;
    const int wm = (w >> 2) * 64, wn = (w & 3) * 32;
    const int gid = lane >> 2, tig = lane & 3;
    #pragma unroll
    for (int i = 0; i < 4; i++) {
        #pragma unroll
        for (int half = 0; half < 2; half++) {
            int r = row0 + wm + i * 16 + gid + half * 8;
            if (mid[r] != m) continue;
            #pragma unroll
            for (int j = 0; j < 4; j++) {
                int c = col0 + wn + j * 8 + tig * 2;
                out[(size_t)r * DMODEL + c]     = acc[i][j][half * 2 + 0];
                out[(size_t)r * DMODEL + c + 1] = acc[i][j][half * 2 + 1];
            }
        }
    }
}

/* ---------------- launch ---------------- */
extern "C" void kernel_launch(void* const* d_in, const int* in_sizes, int n_in,
                              void* d_out, int out_size) {
    (void)in_sizes; (void)n_in; (void)out_size;
    const float* x  = (const float*)d_in[0];
    const float* fc = (const float*)d_in[1];
    const float* Wq = (const float*)d_in[2];
    const float* Wk = (const float*)d_in[3];
    const float* Wv = (const float*)d_in[4];
    const float* Wo = (const float*)d_in[5];
    const int*   mid = (const int*)d_in[6];
    float* out = (float*)d_out;

    prep_kernel<<<4096, 256>>>(x, Wq, Wo);
    wsum_kernel<<<2048, 256>>>(Wk, Wv);
    proj_q_kernel<<<dim3(DMODEL / BN, R_TOK / BM, NMOD), 256>>>(fc, mid);
    proj_kv_kernel<<<dim3((2 * KVE) / BN, R_TOK / BM, NMOD), 256>>>(fc, mid);
    cudaFuncSetAttribute(attn_kernel,
                         cudaFuncAttributeMaxDynamicSharedMemorySize, ATTN_SMEM);
    attn_kernel<<<dim3(SEQ / 64, NH, BDIM), 128, ATTN_SMEM>>>();
    proj_o_kernel<<<dim3(DMODEL / BN, R_TOK / BM, NMOD), 256>>>(mid, out);
}

// round 4
// speedup vs baseline: 4.4058x; 1.3440x over previous
#include <cuda_runtime.h>
#include <math.h>

#define BDIM 2
#define SEQ 2048
#define DMODEL 2048
#define NH 16
#define NKV 4
#define HD 128
#define NMOD 2
#define R_TOK (BDIM*SEQ)      /* 4096 tokens */
#define KVE (NKV*HD)          /* 512 */

/* GEMM tiling */
#define BM 128
#define BN 128
#define BK 16
#define AP 20
#define BP 136
#define GEMM_SMEM_FLOATS (2*BM*AP + 2*BK*BP)

/* ---------------- scratch ---------------- */
__device__ int   g_cnt[NMOD];
__device__ int   g_tok[NMOD*R_TOK];                 /* slot -> token */
__device__ int   g_slot[R_TOK];                     /* token -> m*R_TOK+slot */
__device__ float g_wk[NMOD*DMODEL*KVE];
__device__ float g_wv[NMOD*DMODEL*KVE];
__device__ float g_xt[(size_t)NMOD*R_TOK*DMODEL];   /* gathered tf32 x, slot order */
__device__ float g_wqt[(size_t)NMOD*DMODEL*DMODEL];
__device__ float g_wot[(size_t)NMOD*DMODEL*DMODEL];
__device__ float g_q[(size_t)BDIM*NH*SEQ*HD];
__device__ float g_k[(size_t)BDIM*NKV*SEQ*HD];
__device__ float g_v[(size_t)BDIM*NKV*SEQ*HD];
__device__ float g_attn2[(size_t)NMOD*R_TOK*DMODEL];/* attn out, slot order, fp32 */

/* ---------------- helpers ---------------- */
__device__ __forceinline__ float f2t(float f) {
    unsigned u;
    asm("cvt.rna.tf32.f32 %0, %1;" : "=r"(u) : "f"(f));
    return __uint_as_float(u);
}
__device__ __forceinline__ unsigned f2tu(float f) {
    unsigned u;
    asm("cvt.rna.tf32.f32 %0, %1;" : "=r"(u) : "f"(f));
    return u;
}
__device__ __forceinline__ void mma_tf32(float* d, const unsigned* a, const unsigned* b) {
    asm volatile(
        "mma.sync.aligned.m16n8k8.row.col.f32.tf32.tf32.f32 "
        "{%0,%1,%2,%3},{%4,%5,%6,%7},{%8,%9},{%0,%1,%2,%3};"
        : "+f"(d[0]), "+f"(d[1]), "+f"(d[2]), "+f"(d[3])
        : "r"(a[0]), "r"(a[1]), "r"(a[2]), "r"(a[3]), "r"(b[0]), "r"(b[1]));
}

#define CP16(dst, src) \
    asm volatile("cp.async.cg.shared.global [%0], [%1], 16;" :: "r"(dst), "l"(src))
#define CP_COMMIT() asm volatile("cp.async.commit_group;")
#define CP_WAIT(n)  asm volatile("cp.async.wait_group %0;" :: "n"(n))

/* ---------------- modality gather machinery ---------------- */
__global__ void zero_cnt_kernel() {
    if (threadIdx.x < NMOD) g_cnt[threadIdx.x] = 0;
}
__global__ void assign_kernel(const int* __restrict__ mid) {
    int t = blockIdx.x * blockDim.x + threadIdx.x;
    if (t < R_TOK) {
        int m = mid[t];
        int s = atomicAdd(&g_cnt[m], 1);
        g_tok[m * R_TOK + s] = t;
        g_slot[t] = m * R_TOK + s;
    }
}
__global__ void gather_x_kernel(const float* __restrict__ x) {
    int t = blockIdx.x;
    int dst = g_slot[t];
    const float4* src = (const float4*)(x + (size_t)t * DMODEL);
    float4* d = (float4*)(g_xt + (size_t)dst * DMODEL);
    for (int i = threadIdx.x; i < DMODEL / 4; i += blockDim.x) {
        float4 v = src[i];
        v.x = f2t(v.x); v.y = f2t(v.y); v.z = f2t(v.z); v.w = f2t(v.w);
        d[i] = v;
    }
}
/* zero pad rows [cnt, roundup128(cnt)) of g_xt and g_attn2 */
__global__ void pad_kernel() {
    int m = blockIdx.y;
    int cnt = g_cnt[m];
    int ru = (cnt + BM - 1) & ~(BM - 1);
    int r = cnt + blockIdx.x;
    if (r >= ru) return;
    float4* a = (float4*)(g_xt + ((size_t)m * R_TOK + r) * DMODEL);
    float4* b = (float4*)(g_attn2 + ((size_t)m * R_TOK + r) * DMODEL);
    float4 z = make_float4(0.f, 0.f, 0.f, 0.f);
    for (int i = threadIdx.x; i < DMODEL / 4; i += blockDim.x) { a[i] = z; b[i] = z; }
}

/* ---------------- prepass: tf32-round Wq, Wo ---------------- */
__global__ void prep_kernel(const float* __restrict__ Wq,
                            const float* __restrict__ Wo) {
    const int NE = NMOD * DMODEL * DMODEL;
    for (int i = blockIdx.x * blockDim.x + threadIdx.x; i < 2 * NE;
         i += gridDim.x * blockDim.x) {
        if (i < NE) g_wqt[i]      = f2t(Wq[i]);
        else        g_wot[i - NE] = f2t(Wo[i - NE]);
    }
}

__global__ void wsum_kernel(const float* __restrict__ Wk,
                            const float* __restrict__ Wv) {
    const int n = NMOD * DMODEL * KVE;
    const int half = DMODEL * KVE;
    for (int i = blockIdx.x * blockDim.x + threadIdx.x; i < n;
         i += gridDim.x * blockDim.x) {
        int m = i / half;
        int rest = i - m * half;
        size_t base = (size_t)m * 2 * half + rest;
        g_wk[i] = f2t(Wk[base] + Wk[base + half]);
        g_wv[i] = f2t(Wv[base] + Wv[base + half]);
    }
}

/* ---------------- tf32 GEMM staging ---------------- */
#define GEMM_STAGE_PROLOGUE()                                                 \
    const int tid = threadIdx.x;                                              \
    const int lane = tid & 31, w = tid >> 5;                                  \
    const int wm = (w >> 2) * 64, wn = (w & 3) * 32;                          \
    const int gid = lane >> 2, tig = lane & 3;                                \
    float* As = smem;                                                         \
    float* Bs = smem + 2 * BM * AP;                                           \
    const unsigned sA = (unsigned)__cvta_generic_to_shared(As);               \
    const unsigned sB = (unsigned)__cvta_generic_to_shared(Bs);               \
    auto issue = [&](int buf, int k0) {                                       \
        unsigned aBase = sA + (unsigned)buf * (BM * AP * 4);                  \
        unsigned bBase = sB + (unsigned)buf * (BK * BP * 4);                  \
        for (int q = 0; q < 2; q++) {                                         \
            int fa = tid + q * 256;                                           \
            CP16(aBase + ((fa >> 2) * AP + (fa & 3) * 4) * 4,                 \
                 &X[(size_t)(row0 + (fa >> 2)) * ldx + k0 + (fa & 3) * 4]);   \
            CP16(bBase + ((fa >> 5) * BP + (fa & 31) * 4) * 4,                \
                 &W[(size_t)(k0 + (fa >> 5)) * ldw + col0 + (fa & 31) * 4]);  \
        }                                                                     \
        CP_COMMIT();                                                          \
    };

__device__ __forceinline__ void gemm_tf32(
    const float* __restrict__ X, int ldx,
    const float* __restrict__ W, int ldw,
    int Kdim, int row0, int col0,
    float (&acc)[4][4][4], float* smem)
{
    GEMM_STAGE_PROLOGUE();
    issue(0, 0);
    const int T = Kdim / BK;
    for (int t = 0; t < T; t++) {
        const int buf = t & 1;
        if (t + 1 < T) { issue(buf ^ 1, (t + 1) * BK); CP_WAIT(1); }
        else           { CP_WAIT(0); }
        __syncthreads();
        const float* Ab = As + buf * (BM * AP);
        const float* Bb = Bs + buf * (BK * BP);
        #pragma unroll
        for (int kb = 0; kb < BK; kb += 8) {
            unsigned a[4][4], b[4][2];
            #pragma unroll
            for (int i = 0; i < 4; i++) {
                const float* ap = &Ab[(wm + i * 16 + gid) * AP + kb + tig];
                a[i][0] = __float_as_uint(ap[0]);
                a[i][1] = __float_as_uint(ap[8 * AP]);
                a[i][2] = __float_as_uint(ap[4]);
                a[i][3] = __float_as_uint(ap[8 * AP + 4]);
            }
            #pragma unroll
            for (int j = 0; j < 4; j++) {
                const float* bp = &Bb[(kb + tig) * BP + wn + j * 8 + gid];
                b[j][0] = __float_as_uint(bp[0]);
                b[j][1] = __float_as_uint(bp[4 * BP]);
            }
            #pragma unroll
            for (int i = 0; i < 4; i++)
                #pragma unroll
                for (int j = 0; j < 4; j++)
                    mma_tf32(acc[i][j], a[i], b[j]);
        }
        __syncthreads();
    }
}

__device__ __forceinline__ void gemm_tf32_splitA(
    const float* __restrict__ X, int ldx,
    const float* __restrict__ W, int ldw,
    int Kdim, int row0, int col0,
    float (&acc)[4][4][4], float* smem)
{
    GEMM_STAGE_PROLOGUE();
    issue(0, 0);
    const int T = Kdim / BK;
    for (int t = 0; t < T; t++) {
        const int buf = t & 1;
        if (t + 1 < T) { issue(buf ^ 1, (t + 1) * BK); CP_WAIT(1); }
        else           { CP_WAIT(0); }
        __syncthreads();
        const float* Ab = As + buf * (BM * AP);
        const float* Bb = Bs + buf * (BK * BP);
        #pragma unroll
        for (int kb = 0; kb < BK; kb += 8) {
            unsigned b[4][2];
            #pragma unroll
            for (int j = 0; j < 4; j++) {
                const float* bp = &Bb[(kb + tig) * BP + wn + j * 8 + gid];
                b[j][0] = __float_as_uint(bp[0]);
                b[j][1] = __float_as_uint(bp[4 * BP]);
            }
            #pragma unroll
            for (int i = 0; i < 4; i++) {
                const float* ap = &Ab[(wm + i * 16 + gid) * AP + kb + tig];
                float v[4] = {ap[0], ap[8 * AP], ap[4], ap[8 * AP + 4]};
                unsigned ah[4], al[4];
                #pragma unroll
                for (int q = 0; q < 4; q++) {
                    ah[q] = f2tu(v[q]);
                    al[q] = f2tu(v[q] - __uint_as_float(ah[q]));
                }
                #pragma unroll
                for (int j = 0; j < 4; j++) {
                    mma_tf32(acc[i][j], ah, b[j]);
                    mma_tf32(acc[i][j], al, b[j]);
                }
            }
        }
        __syncthreads();
    }
}

/* ---------------- Q projection + RoPE (gathered) ---------------- */
__global__ void __launch_bounds__(256, 2) proj_q_kernel(
    const float* __restrict__ fc)
{
    __shared__ float smem[GEMM_SMEM_FLOATS];
    const int m = blockIdx.z;
    const int cnt = g_cnt[m];
    const int row0 = blockIdx.y * BM, col0 = blockIdx.x * BN;
    if (row0 >= cnt) return;
    float acc[4][4][4] = {};
    gemm_tf32(g_xt + (size_t)m * R_TOK * DMODEL, DMODEL,
              g_wqt + (size_t)m * DMODEL * DMODEL, DMODEL,
              DMODEL, row0, col0, acc, smem);

    const int lane = threadIdx.x & 31, w = threadIdx.x >> 5;
    const int wm = (w >> 2) * 64, wn = (w & 3) * 32;
    const int gid = lane >> 2, tig = lane & 3;
    #pragma unroll
    for (int i = 0; i < 4; i++) {
        #pragma unroll
        for (int half = 0; half < 2; half++) {
            int r = row0 + wm + i * 16 + gid + half * 8;
            if (r >= cnt) continue;
            int tok = g_tok[m * R_TOK + r];
            int b_ = tok >> 11, s = tok & (SEQ - 1);
            #pragma unroll
            for (int j = 0; j < 4; j++) {
                int c = col0 + wn + j * 8 + tig * 2;
                float e = acc[i][j][half * 2 + 0];
                float o = acc[i][j][half * 2 + 1];
                int h = c >> 7, d = c & 127, pr = d >> 1;
                float cv = fc[(size_t)s * 256 + pr * 4 + 0];
                float sv = fc[(size_t)s * 256 + pr * 4 + 2];
                size_t base = (((size_t)b_ * NH + h) * SEQ + s) * HD + d;
                g_q[base]     = e * cv + o * sv;
                g_q[base + 1] = o * cv - e * sv;
            }
        }
    }
}

/* ---------------- K/V projection (+RoPE on K, gathered) ---------------- */
__global__ void __launch_bounds__(256, 2) proj_kv_kernel(
    const float* __restrict__ fc)
{
    __shared__ float smem[GEMM_SMEM_FLOATS];
    const int m = blockIdx.z;
    const int cnt = g_cnt[m];
    const int row0 = blockIdx.y * BM;
    if (row0 >= cnt) return;
    const int n0 = blockIdx.x * BN;
    const bool isV = (n0 >= KVE);
    const float* W = (isV ? g_wv : g_wk) + (size_t)m * DMODEL * KVE;
    const int c0base = isV ? n0 - KVE : n0;

    float acc[4][4][4] = {};
    gemm_tf32(g_xt + (size_t)m * R_TOK * DMODEL, DMODEL,
              W, KVE, DMODEL, row0, c0base, acc, smem);

    const int lane = threadIdx.x & 31, w = threadIdx.x >> 5;
    const int wm = (w >> 2) * 64, wn = (w & 3) * 32;
    const int gid = lane >> 2, tig = lane & 3;
    #pragma unroll
    for (int i = 0; i < 4; i++) {
        #pragma unroll
        for (int half = 0; half < 2; half++) {
            int r = row0 + wm + i * 16 + gid + half * 8;
            if (r >= cnt) continue;
            int tok = g_tok[m * R_TOK + r];
            int b_ = tok >> 11, s = tok & (SEQ - 1);
            #pragma unroll
            for (int j = 0; j < 4; j++) {
                int c = c0base + wn + j * 8 + tig * 2;
                int kvh = c >> 7, d = c & 127;
                float e = acc[i][j][half * 2 + 0];
                float o = acc[i][j][half * 2 + 1];
                size_t base = (((size_t)b_ * NKV + kvh) * SEQ + s) * HD + d;
                if (!isV) {
                    int pr = d >> 1;
                    float cv = fc[(size_t)s * 256 + pr * 4 + 0];
                    float sv = fc[(size_t)s * 256 + pr * 4 + 2];
                    g_k[base]     = e * cv + o * sv;
                    g_k[base + 1] = o * cv - e * sv;
                } else {
                    g_v[base]     = e;
                    g_v[base + 1] = o;
                }
            }
        }
    }
}

/* ---------------- flash attention, tf32 tensor cores ---------------- */
#define KP 132
#define VP 136
#define PP 68
#define ATTN_SMEM ((64*KP + 64*VP + 64*PP) * 4)

__global__ void __launch_bounds__(128, 2) attn_kernel() {
    extern __shared__ float sm[];
    float* Ks = sm;
    float* Vs = Ks + 64 * KP;
    float* Ps = Vs + 64 * VP;

    const int qt = blockIdx.x, h = blockIdx.y, b = blockIdx.z;
    const int kvh = h >> 2;
    const int tid = threadIdx.x;
    const int w = tid >> 5, lane = tid & 31, gid = lane >> 2, tig = lane & 3;
    const float scale = 0.08838834764831845f;

    const float* Qg = g_q + (((size_t)b * NH + h) * SEQ + qt * 64 + w * 16) * HD;
    unsigned QA[16][4];
    #pragma unroll
    for (int ks = 0; ks < 16; ks++) {
        QA[ks][0] = f2tu(Qg[gid * HD + 8 * ks + tig] * scale);
        QA[ks][1] = f2tu(Qg[(gid + 8) * HD + 8 * ks + tig] * scale);
        QA[ks][2] = f2tu(Qg[gid * HD + 8 * ks + tig + 4] * scale);
        QA[ks][3] = f2tu(Qg[(gid + 8) * HD + 8 * ks + tig + 4] * scale);
    }

    float o[16][4];
    #pragma unroll
    for (int n = 0; n < 16; n++)
        #pragma unroll
        for (int q = 0; q < 4; q++) o[n][q] = 0.f;
    float mo[2] = {-1e30f, -1e30f}, l[2] = {0.f, 0.f};

    const float* Kg = g_k + ((size_t)b * NKV + kvh) * SEQ * HD;
    const float* Vg = g_v + ((size_t)b * NKV + kvh) * SEQ * HD;
    float* Pw = Ps + w * 16 * PP;

    for (int kt = 0; kt < SEQ / 64; kt++) {
        __syncthreads();
        const float* Kt = Kg + (size_t)kt * 64 * HD;
        const float* Vt = Vg + (size_t)kt * 64 * HD;
        #pragma unroll
        for (int it = 0; it < 16; it++) {
            int i = tid + it * 128;
            int r = i >> 5, c4 = (i & 31) << 2;
            float4 kv4 = *(const float4*)&Kt[r * HD + c4];
            float4 vv4 = *(const float4*)&Vt[r * HD + c4];
            kv4.x = f2t(kv4.x); kv4.y = f2t(kv4.y);
            kv4.z = f2t(kv4.z); kv4.w = f2t(kv4.w);
            vv4.x = f2t(vv4.x); vv4.y = f2t(vv4.y);
            vv4.z = f2t(vv4.z); vv4.w = f2t(vv4.w);
            *(float4*)&Ks[r * KP + c4] = kv4;
            *(float4*)&Vs[r * VP + c4] = vv4;
        }
        __syncthreads();

        float s[8][4] = {};
        #pragma unroll
        for (int ks = 0; ks < 16; ks++) {
            #pragma unroll
            for (int j = 0; j < 8; j++) {
                unsigned b2[2];
                b2[0] = __float_as_uint(Ks[(j * 8 + gid) * KP + ks * 8 + tig]);
                b2[1] = __float_as_uint(Ks[(j * 8 + gid) * KP + ks * 8 + tig + 4]);
                mma_tf32(s[j], QA[ks], b2);
            }
        }

        #pragma unroll
        for (int rr = 0; rr < 2; rr++) {
            float mx = -1e30f;
            #pragma unroll
            for (int j = 0; j < 8; j++)
                mx = fmaxf(mx, fmaxf(s[j][2 * rr], s[j][2 * rr + 1]));
            mx = fmaxf(mx, __shfl_xor_sync(0xffffffffu, mx, 1));
            mx = fmaxf(mx, __shfl_xor_sync(0xffffffffu, mx, 2));
            float mnew = fmaxf(mo[rr], mx);
            float corr = __expf(mo[rr] - mnew);
            float rs = 0.f;
            #pragma unroll
            for (int j = 0; j < 8; j++) {
                float p0 = f2t(__expf(s[j][2 * rr] - mnew));
                float p1 = f2t(__expf(s[j][2 * rr + 1] - mnew));
                s[j][2 * rr] = p0; s[j][2 * rr + 1] = p1;
                rs += p0 + p1;
            }
            rs += __shfl_xor_sync(0xffffffffu, rs, 1);
            rs += __shfl_xor_sync(0xffffffffu, rs, 2);
            l[rr] = l[rr] * corr + rs;
            mo[rr] = mnew;
            #pragma unroll
            for (int n = 0; n < 16; n++) {
                o[n][2 * rr] *= corr; o[n][2 * rr + 1] *= corr;
            }
        }

        #pragma unroll
        for (int j = 0; j < 8; j++) {
            *(float2*)&Pw[gid * PP + j * 8 + 2 * tig] =
                make_float2(s[j][0], s[j][1]);
            *(float2*)&Pw[(gid + 8) * PP + j * 8 + 2 * tig] =
                make_float2(s[j][2], s[j][3]);
        }
        __syncwarp();

        #pragma unroll
        for (int kk = 0; kk < 8; kk++) {
            unsigned a[4];
            a[0] = __float_as_uint(Pw[gid * PP + kk * 8 + tig]);
            a[1] = __float_as_uint(Pw[(gid + 8) * PP + kk * 8 + tig]);
            a[2] = __float_as_uint(Pw[gid * PP + kk * 8 + tig + 4]);
            a[3] = __float_as_uint(Pw[(gid + 8) * PP + kk * 8 + tig + 4]);
            #pragma unroll
            for (int n = 0; n < 16; n++) {
                unsigned b2[2];
                b2[0] = __float_as_uint(Vs[(kk * 8 + tig) * VP + n * 8 + gid]);
                b2[1] = __float_as_uint(Vs[(kk * 8 + tig + 4) * VP + n * 8 + gid]);
                mma_tf32(o[n], a, b2);
            }
        }
    }

    /* epilogue: normalize and write directly in SLOT order for proj_o */
    int t0 = b * SEQ + qt * 64 + w * 16 + gid;
    int t1 = t0 + 8;
    size_t r0 = (size_t)g_slot[t0] * DMODEL + h * HD;
    size_t r1 = (size_t)g_slot[t1] * DMODEL + h * HD;
    float inv0 = 1.f / l[0], inv1 = 1.f / l[1];
    #pragma unroll
    for (int n = 0; n < 16; n++) {
        *(float2*)&g_attn2[r0 + n * 8 + 2 * tig] =
            make_float2(o[n][0] * inv0, o[n][1] * inv0);
        *(float2*)&g_attn2[r1 + n * 8 + 2 * tig] =
            make_float2(o[n][2] * inv1, o[n][3] * inv1);
    }
}

/* ---------------- output projection (split-A, gathered) ---------------- */
__global__ void __launch_bounds__(256, 2) proj_o_kernel(float* __restrict__ out)
{
    __shared__ float smem[GEMM_SMEM_FLOATS];
    const int m = blockIdx.z;
    const int cnt = g_cnt[m];
    const int row0 = blockIdx.y * BM, col0 = blockIdx.x * BN;
    if (row0 >= cnt) return;
    float acc[4][4][4] = {};
    gemm_tf32_splitA(g_attn2 + (size_t)m * R_TOK * DMODEL, DMODEL,
                     g_wot + (size_t)m * DMODEL * DMODEL, DMODEL,
                     DMODEL, row0, col0, acc, smem);

    const int lane = threadIdx.x & 31, w = threadIdx.x >> 5;
    const int wm = (w >> 2) * 64, wn = (w & 3) * 32;
    const int gid = lane >> 2, tig = lane & 3;
    #pragma unroll
    for (int i = 0; i < 4; i++) {
        #pragma unroll
        for (int half = 0; half < 2; half++) {
            int r = row0 + wm + i * 16 + gid + half * 8;
            if (r >= cnt) continue;
            int tok = g_tok[m * R_TOK + r];
            #pragma unroll
            for (int j = 0; j < 4; j++) {
                int c = col0 + wn + j * 8 + tig * 2;
                out[(size_t)tok * DMODEL + c]     = acc[i][j][half * 2 + 0];
                out[(size_t)tok * DMODEL + c + 1] = acc[i][j][half * 2 + 1];
            }
        }
    }
}

/* ---------------- launch ---------------- */
extern "C" void kernel_launch(void* const* d_in, const int* in_sizes, int n_in,
                              void* d_out, int out_size) {
    (void)in_sizes; (void)n_in; (void)out_size;
    const float* x  = (const float*)d_in[0];
    const float* fc = (const float*)d_in[1];
    const float* Wq = (const float*)d_in[2];
    const float* Wk = (const float*)d_in[3];
    const float* Wv = (const float*)d_in[4];
    const float* Wo = (const float*)d_in[5];
    const int*   mid = (const int*)d_in[6];
    float* out = (float*)d_out;

    zero_cnt_kernel<<<1, 32>>>();
    assign_kernel<<<R_TOK / 256, 256>>>(mid);
    gather_x_kernel<<<R_TOK, 256>>>(x);
    pad_kernel<<<dim3(BM, NMOD), 256>>>();
    prep_kernel<<<4096, 256>>>(Wq, Wo);
    wsum_kernel<<<2048, 256>>>(Wk, Wv);
    proj_q_kernel<<<dim3(DMODEL / BN, R_TOK / BM, NMOD), 256>>>(fc);
    proj_kv_kernel<<<dim3((2 * KVE) / BN, R_TOK / BM, NMOD), 256>>>(fc);
    cudaFuncSetAttribute(attn_kernel,
                         cudaFuncAttributeMaxDynamicSharedMemorySize, ATTN_SMEM);
    attn_kernel<<<dim3(SEQ / 64, NH, BDIM), 128, ATTN_SMEM>>>();
    proj_o_kernel<<<dim3(DMODEL / BN, R_TOK / BM, NMOD), 256>>>(out);
}